// round 9
// baseline (speedup 1.0000x reference)
#include <cuda_runtime.h>
#include <cuda_fp16.h>
#include <cstdint>

#define DIM     512
#define HEADS   8
#define DH      64
#define BATCH   8
#define NWIN    64
#define WSZ     64
#define NTOK    (BATCH * NWIN * WSZ)   // 32768

// Scratch (allocation-free rule: __device__ globals)
__device__ __half g_xh[(size_t)NTOK * DIM];                       // 33.5 MB
__device__ __half g_qkvh[(size_t)NTOK * 3 * DIM];                 // 100 MB
__device__ __half g_attnh[(size_t)NTOK * DIM];                    // 33.5 MB
__device__ __half g_wth[(size_t)(3 * DIM) * DIM + DIM * DIM];     // 2 MB (wqkvT, wprojT)

// ---------------------------------------------------------------------------
// helpers
// ---------------------------------------------------------------------------
__device__ __forceinline__ uint32_t smem_u32(const void* p) {
    uint32_t a;
    asm("{ .reg .u64 t; cvta.to.shared.u64 t, %1; cvt.u32.u64 %0, t; }"
        : "=r"(a) : "l"(p));
    return a;
}

__device__ __forceinline__ void cp16(uint32_t dst, const void* src) {
    asm volatile("cp.async.cg.shared.global [%0], [%1], 16;"
                 :: "r"(dst), "l"(src) : "memory");
}

__device__ __forceinline__ void ldsm4(unsigned r[4], uint32_t a) {
    asm volatile("ldmatrix.sync.aligned.m8n8.x4.shared.b16 {%0,%1,%2,%3}, [%4];"
                 : "=r"(r[0]), "=r"(r[1]), "=r"(r[2]), "=r"(r[3]) : "r"(a));
}

__device__ __forceinline__ void ldsm4t(unsigned r[4], uint32_t a) {
    asm volatile("ldmatrix.sync.aligned.m8n8.x4.trans.shared.b16 {%0,%1,%2,%3}, [%4];"
                 : "=r"(r[0]), "=r"(r[1]), "=r"(r[2]), "=r"(r[3]) : "r"(a));
}

__device__ __forceinline__ void mma_f16(float c[4], const unsigned a[4],
                                        const unsigned b[2]) {
    asm volatile(
        "mma.sync.aligned.m16n8k16.row.col.f32.f16.f16.f32 "
        "{%0,%1,%2,%3}, {%4,%5,%6,%7}, {%8,%9}, {%0,%1,%2,%3};"
        : "+f"(c[0]), "+f"(c[1]), "+f"(c[2]), "+f"(c[3])
        : "r"(a[0]), "r"(a[1]), "r"(a[2]), "r"(a[3]), "r"(b[0]), "r"(b[1]));
}

// ---------------------------------------------------------------------------
// Prologue: fp32 -> fp16 convert (x), fp32 -> fp16 transpose (weights)
// ---------------------------------------------------------------------------
__global__ void f2h_copy(const float* __restrict__ in, __half* __restrict__ out,
                         int n4)
{
    const int i = blockIdx.x * blockDim.x + threadIdx.x;
    if (i < n4) {
        float4 v = ((const float4*)in)[i];
        __half2* o = (__half2*)(out + (size_t)i * 4);
        o[0] = __floats2half2_rn(v.x, v.y);
        o[1] = __floats2half2_rn(v.z, v.w);
    }
}

__global__ void transpose_h(const float* __restrict__ in,
                            __half* __restrict__ out, int R, int C)
{
    __shared__ float t[32][33];
    const int tx = threadIdx.x, ty = threadIdx.y;
    const int x = blockIdx.x * 32 + tx;
    #pragma unroll
    for (int j = 0; j < 32; j += 8)
        t[ty + j][tx] = in[(size_t)(blockIdx.y * 32 + ty + j) * C + x];
    __syncthreads();
    const int x2 = blockIdx.y * 32 + tx;
    #pragma unroll
    for (int j = 0; j < 32; j += 8)
        out[(size_t)(blockIdx.x * 32 + ty + j) * R + x2] =
            __float2half_rn(t[tx][ty + j]);
}

// ---------------------------------------------------------------------------
// fp16 GEMM: C[M,N] = A[M,K] @ Bt[N,K]^T (+bias).  A, Bt half row-major.
// 128x128 CTA tile, BK=64, 3-stage cp.async, 128 thr / 4 warps,
// 64x64 warp tiles (8 ldmatrix -> 32 HMMA per ks: 32 FLOP per smem byte).
// ---------------------------------------------------------------------------
#define ST_H      72
#define TILE_H    (128 * ST_H)                 // halves per operand stage
#define NSTAGE    3
#define GEMM_SMEM (NSTAGE * 2 * TILE_H * 2)    // 110592 bytes

__global__ __launch_bounds__(128, 2) void gemm_h(
    const __half* __restrict__ A, const __half* __restrict__ Bt,
    const float* __restrict__ bias, void* __restrict__ Cout,
    int M, int N, int K, int out_half)
{
    extern __shared__ __align__(16) __half smh[];
    __half* As = smh;                       // [3][128][72]
    __half* Bs = smh + NSTAGE * TILE_H;     // [3][128][72]
    const uint32_t as_a = smem_u32(As);
    const uint32_t bs_a = smem_u32(Bs);

    const int tid  = threadIdx.x;
    const int lane = tid & 31;
    const int wid  = tid >> 5;               // 0..3
    const int wm   = (wid & 1) * 64;
    const int wn   = (wid >> 1) * 64;
    const int bm   = blockIdx.y * 128;
    const int bn   = blockIdx.x * 128;
    const int q    = lane & 3;
    const int g    = lane >> 2;

    // per-lane ldmatrix byte offsets within a stage
    const int m8  = lane & 7;
    const int sel = lane >> 3;
    uint32_t a_off[4], b_off[4];
    #pragma unroll
    for (int mt = 0; mt < 4; mt++)
        a_off[mt] = (uint32_t)(((wm + mt * 16 + ((sel & 1) << 3) + m8) * ST_H
                                + ((sel >> 1) << 3)) * 2);
    #pragma unroll
    for (int p = 0; p < 4; p++)
        b_off[p] = (uint32_t)(((wn + ((p << 1) + (sel >> 1)) * 8 + m8) * ST_H
                               + ((sel & 1) << 3)) * 2);

    float acc[4][8][4];
    #pragma unroll
    for (int i = 0; i < 4; i++)
        #pragma unroll
        for (int j = 0; j < 8; j++)
            #pragma unroll
            for (int k = 0; k < 4; k++) acc[i][j][k] = 0.f;

    const int NT = K >> 6;

    #define LOAD_STAGE(kt_)                                                     \
    do {                                                                        \
        const int s_  = (kt_) % NSTAGE;                                         \
        const int k0_ = (kt_) * 64;                                             \
        _Pragma("unroll")                                                       \
        for (int i_ = 0; i_ < 4; i_++) {                                        \
            const int idx_ = tid + i_ * 128;    /* 0..511 */                    \
            const int row_ = idx_ >> 2;         /* 0..127 */                    \
            const int c_   = (idx_ & 3) * 16;   /* halves: 0,16,32,48 */        \
            cp16(as_a + (uint32_t)(s_ * TILE_H + row_ * ST_H + c_) * 2,         \
                 A + (size_t)(bm + row_) * K + k0_ + c_);                       \
            cp16(as_a + (uint32_t)(s_ * TILE_H + row_ * ST_H + c_ + 8) * 2,     \
                 A + (size_t)(bm + row_) * K + k0_ + c_ + 8);                   \
            cp16(bs_a + (uint32_t)(s_ * TILE_H + row_ * ST_H + c_) * 2,         \
                 Bt + (size_t)(bn + row_) * K + k0_ + c_);                      \
            cp16(bs_a + (uint32_t)(s_ * TILE_H + row_ * ST_H + c_ + 8) * 2,     \
                 Bt + (size_t)(bn + row_) * K + k0_ + c_ + 8);                  \
        }                                                                       \
        asm volatile("cp.async.commit_group;" ::: "memory");                    \
    } while (0)

    LOAD_STAGE(0);
    LOAD_STAGE(1);

    for (int kt = 0; kt < NT; kt++) {
        if (kt < NT - 1)
            asm volatile("cp.async.wait_group 1;" ::: "memory");
        else
            asm volatile("cp.async.wait_group 0;" ::: "memory");
        __syncthreads();
        if (kt + 2 < NT) LOAD_STAGE(kt + 2);

        const int st = kt % NSTAGE;
        const uint32_t sa = as_a + (uint32_t)(st * TILE_H) * 2;
        const uint32_t sb = bs_a + (uint32_t)(st * TILE_H) * 2;

        #pragma unroll
        for (int ks = 0; ks < 4; ks++) {
            const uint32_t ko = (uint32_t)(ks * 32);   // 16 halves = 32 bytes
            unsigned afr[4][4], bfr[8][2];
            #pragma unroll
            for (int mt = 0; mt < 4; mt++)
                ldsm4(afr[mt], sa + a_off[mt] + ko);
            #pragma unroll
            for (int p = 0; p < 4; p++) {
                unsigned t[4];
                ldsm4(t, sb + b_off[p] + ko);
                bfr[2 * p][0] = t[0]; bfr[2 * p][1] = t[1];
                bfr[2 * p + 1][0] = t[2]; bfr[2 * p + 1][1] = t[3];
            }
            #pragma unroll
            for (int mt = 0; mt < 4; mt++)
                #pragma unroll
                for (int nt = 0; nt < 8; nt++)
                    mma_f16(acc[mt][nt], afr[mt], bfr[nt]);
        }
    }

    // Epilogue: c0,c1 -> (row g, cols 2q,2q+1); c2,c3 -> row g+8.
    if (out_half) {
        __half* Ch = (__half*)Cout;
        #pragma unroll
        for (int nt = 0; nt < 8; nt++) {
            const int col = bn + wn + nt * 8 + 2 * q;
            #pragma unroll
            for (int mt = 0; mt < 4; mt++) {
                const int r0 = bm + wm + mt * 16 + g;
                *(__half2*)(Ch + (size_t)r0 * N + col) =
                    __floats2half2_rn(acc[mt][nt][0], acc[mt][nt][1]);
                *(__half2*)(Ch + (size_t)(r0 + 8) * N + col) =
                    __floats2half2_rn(acc[mt][nt][2], acc[mt][nt][3]);
            }
        }
    } else {
        float* Cf = (float*)Cout;
        #pragma unroll
        for (int nt = 0; nt < 8; nt++) {
            const int col = bn + wn + nt * 8 + 2 * q;
            float b0 = 0.f, b1 = 0.f;
            if (bias) { b0 = bias[col]; b1 = bias[col + 1]; }
            #pragma unroll
            for (int mt = 0; mt < 4; mt++) {
                const int r0 = bm + wm + mt * 16 + g;
                *(float2*)(Cf + (size_t)r0 * N + col) =
                    make_float2(acc[mt][nt][0] + b0, acc[mt][nt][1] + b1);
                *(float2*)(Cf + (size_t)(r0 + 8) * N + col) =
                    make_float2(acc[mt][nt][2] + b0, acc[mt][nt][3] + b1);
            }
        }
    }
}

// ---------------------------------------------------------------------------
// Window attention: all-fp16 operands, mma.m16n8k16, ldmatrix (+.trans for V).
// One 128-thr block per (b,h,n). Warp w owns rows 16w..16w+15. (unchanged)
// ---------------------------------------------------------------------------
__global__ __launch_bounds__(128) void window_attn_h(
    const __half* __restrict__ qkv, __half* __restrict__ out)
{
    __shared__ __half Qh[64][ST_H];    // Q, then P
    __shared__ __half KVh[64][ST_H];   // K, then V

    const int tid  = threadIdx.x;
    const int lane = tid & 31;
    const int w    = tid >> 5;
    const int g    = lane >> 2;
    const int q    = lane & 3;
    const int m8   = lane & 7;
    const int sel  = lane >> 3;

    const int idx = blockIdx.x;
    const int n   = idx & 63;
    const int h   = (idx >> 6) & 7;
    const int b   = idx >> 9;
    const size_t tokbase = ((size_t)(b * NWIN + n) * WSZ) * (3 * DIM);

    const uint32_t qbase = smem_u32(Qh);
    const uint32_t kbase = smem_u32(KVh);

    // Load Q,K raw half into smem; prefetch V to registers.
    uint4 vpre[4];
    #pragma unroll
    for (int i = 0; i < 4; i++) {
        const int lin = i * 128 + tid;      // 0..511
        const int row = lin >> 3;           // 0..63
        const int c8  = (lin & 7) * 8;      // halves 0..56
        const __half* src = qkv + tokbase + (size_t)row * (3 * DIM) + h * DH + c8;
        *(uint4*)&Qh[row][c8]  = *(const uint4*)src;
        *(uint4*)&KVh[row][c8] = *(const uint4*)(src + DIM);
        vpre[i] = *(const uint4*)(src + 2 * DIM);
    }
    __syncthreads();

    // ldmatrix per-lane offsets (bytes)
    const uint32_t aoff =
        (uint32_t)(((w * 16 + ((sel & 1) << 3) + m8) * ST_H + ((sel >> 1) << 3)) * 2);
    uint32_t boff[4], voff[4];
    #pragma unroll
    for (int p = 0; p < 4; p++) {
        boff[p] = (uint32_t)(((((p << 1) + (sel >> 1)) * 8 + m8) * ST_H
                              + ((sel & 1) << 3)) * 2);
        voff[p] = (uint32_t)(((((sel & 1) << 3) + m8) * ST_H
                              + ((p << 1) + (sel >> 1)) * 8) * 2);
    }

    // S = Q K^T
    float sacc[8][4];
    #pragma unroll
    for (int nt = 0; nt < 8; nt++)
        #pragma unroll
        for (int j = 0; j < 4; j++) sacc[nt][j] = 0.f;

    #pragma unroll
    for (int ks = 0; ks < 4; ks++) {
        const uint32_t ko = (uint32_t)(ks * 32);
        unsigned a[4], bfr[8][2];
        ldsm4(a, qbase + aoff + ko);
        #pragma unroll
        for (int p = 0; p < 4; p++) {
            unsigned t[4];
            ldsm4(t, kbase + boff[p] + ko);
            bfr[2 * p][0] = t[0]; bfr[2 * p][1] = t[1];
            bfr[2 * p + 1][0] = t[2]; bfr[2 * p + 1][1] = t[3];
        }
        #pragma unroll
        for (int nt = 0; nt < 8; nt++)
            mma_f16(sacc[nt], a, bfr[nt]);
    }

    // Register softmax (rows warp-private): thread owns rows r=g(+8), cols 2q..
    const float scale = 0.125f;
    float mx0 = -1e30f, mx1 = -1e30f;
    #pragma unroll
    for (int nt = 0; nt < 8; nt++) {
        #pragma unroll
        for (int j = 0; j < 4; j++) sacc[nt][j] *= scale;
        mx0 = fmaxf(mx0, fmaxf(sacc[nt][0], sacc[nt][1]));
        mx1 = fmaxf(mx1, fmaxf(sacc[nt][2], sacc[nt][3]));
    }
    mx0 = fmaxf(mx0, __shfl_xor_sync(0xffffffffu, mx0, 1));
    mx0 = fmaxf(mx0, __shfl_xor_sync(0xffffffffu, mx0, 2));
    mx1 = fmaxf(mx1, __shfl_xor_sync(0xffffffffu, mx1, 1));
    mx1 = fmaxf(mx1, __shfl_xor_sync(0xffffffffu, mx1, 2));

    float s0 = 0.f, s1 = 0.f;
    #pragma unroll
    for (int nt = 0; nt < 8; nt++) {
        sacc[nt][0] = __expf(sacc[nt][0] - mx0);
        sacc[nt][1] = __expf(sacc[nt][1] - mx0);
        sacc[nt][2] = __expf(sacc[nt][2] - mx1);
        sacc[nt][3] = __expf(sacc[nt][3] - mx1);
        s0 += sacc[nt][0] + sacc[nt][1];
        s1 += sacc[nt][2] + sacc[nt][3];
    }
    s0 += __shfl_xor_sync(0xffffffffu, s0, 1);
    s0 += __shfl_xor_sync(0xffffffffu, s0, 2);
    s1 += __shfl_xor_sync(0xffffffffu, s1, 1);
    s1 += __shfl_xor_sync(0xffffffffu, s1, 2);
    const float inv0 = 1.f / s0, inv1 = 1.f / s1;

    // P -> Qh (half, warp-private rows)
    {
        const int r = w * 16 + g;
        #pragma unroll
        for (int nt = 0; nt < 8; nt++) {
            const int col = nt * 8 + 2 * q;
            *(__half2*)&Qh[r][col] =
                __floats2half2_rn(sacc[nt][0] * inv0, sacc[nt][1] * inv0);
            *(__half2*)&Qh[r + 8][col] =
                __floats2half2_rn(sacc[nt][2] * inv1, sacc[nt][3] * inv1);
        }
    }
    __syncthreads();   // all warps' K reads complete before V overwrites KVh

    // V -> KVh (raw half)
    #pragma unroll
    for (int i = 0; i < 4; i++) {
        const int lin = i * 128 + tid;
        const int row = lin >> 3;
        const int c8  = (lin & 7) * 8;
        *(uint4*)&KVh[row][c8] = vpre[i];
    }
    __syncthreads();

    // O = P V  (V via ldmatrix.trans)
    float oacc[8][4];
    #pragma unroll
    for (int nt = 0; nt < 8; nt++)
        #pragma unroll
        for (int j = 0; j < 4; j++) oacc[nt][j] = 0.f;

    #pragma unroll
    for (int ks = 0; ks < 4; ks++) {
        const uint32_t ko  = (uint32_t)(ks * 32);               // P: +16 cols
        const uint32_t kov = (uint32_t)(ks * 16 * ST_H * 2);    // V: +16 rows
        unsigned a[4], bfr[8][2];
        ldsm4(a, qbase + aoff + ko);
        #pragma unroll
        for (int p = 0; p < 4; p++) {
            unsigned t[4];
            ldsm4t(t, kbase + voff[p] + kov);
            bfr[2 * p][0] = t[0]; bfr[2 * p][1] = t[1];
            bfr[2 * p + 1][0] = t[2]; bfr[2 * p + 1][1] = t[3];
        }
        #pragma unroll
        for (int nt = 0; nt < 8; nt++)
            mma_f16(oacc[nt], a, bfr[nt]);
    }

    // O -> half, [B,H,NW,W,dh] linear layout (free reshape for proj GEMM)
    const size_t obase = (((size_t)(b * HEADS + h) * NWIN + n) * WSZ) * DH;
    const int r = w * 16 + g;
    #pragma unroll
    for (int nt = 0; nt < 8; nt++) {
        const int col = nt * 8 + 2 * q;
        *(__half2*)(out + obase + (size_t)r * DH + col) =
            __floats2half2_rn(oacc[nt][0], oacc[nt][1]);
        *(__half2*)(out + obase + (size_t)(r + 8) * DH + col) =
            __floats2half2_rn(oacc[nt][2], oacc[nt][3]);
    }
}

// ---------------------------------------------------------------------------
extern "C" void kernel_launch(void* const* d_in, const int* in_sizes, int n_in,
                              void* d_out, int out_size)
{
    const float* x      = (const float*)d_in[0];  // [8,64,64,512]
    const float* w_qkv  = (const float*)d_in[1];  // [512,1536]
    const float* w_proj = (const float*)d_in[2];  // [512,512]
    const float* b_proj = (const float*)d_in[3];  // [512]
    float* out = (float*)d_out;                   // [8,64,64,512]

    __half *xh, *qkvh, *attnh, *wth;
    cudaGetSymbolAddress((void**)&xh,    g_xh);
    cudaGetSymbolAddress((void**)&qkvh,  g_qkvh);
    cudaGetSymbolAddress((void**)&attnh, g_attnh);
    cudaGetSymbolAddress((void**)&wth,   g_wth);
    __half* wqkvT_h  = wth;                            // [1536,512]
    __half* wprojT_h = wth + (size_t)(3 * DIM) * DIM;  // [512,512]

    static bool attr_set = false;
    if (!attr_set) {
        cudaFuncSetAttribute(gemm_h,
                             cudaFuncAttributeMaxDynamicSharedMemorySize, GEMM_SMEM);
        attr_set = true;
    }

    // 0) prologue: x -> half; weights -> transposed half
    {
        const int n4 = NTOK * DIM / 4;
        f2h_copy<<<(n4 + 255) / 256, 256>>>(x, xh, n4);
        dim3 blk(32, 8);
        transpose_h<<<dim3((3 * DIM) / 32, DIM / 32), blk>>>(w_qkv, wqkvT_h, DIM, 3 * DIM);
        transpose_h<<<dim3(DIM / 32, DIM / 32), blk>>>(w_proj, wprojT_h, DIM, DIM);
    }
    // 1) qkv = x @ w_qkv (fp16 in, fp16 out)
    {
        dim3 grid((3 * DIM) / 128, NTOK / 128);
        gemm_h<<<grid, 128, GEMM_SMEM>>>(xh, wqkvT_h, nullptr, qkvh,
                                         NTOK, 3 * DIM, DIM, 1);
    }
    // 2) per-window attention -> [B,H,NW,W,dh] linear
    {
        window_attn_h<<<BATCH * HEADS * NWIN, 128>>>(qkvh, attnh);
    }
    // 3) out = attn_flat @ w_proj + b_proj (fp16 in, fp32 out)
    {
        dim3 grid(DIM / 128, NTOK / 128);
        gemm_h<<<grid, 128, GEMM_SMEM>>>(attnh, wprojT_h, b_proj, out,
                                         NTOK, DIM, DIM, 0);
    }
}

// round 10
// speedup vs baseline: 1.0022x; 1.0022x over previous
#include <cuda_runtime.h>
#include <cuda_fp16.h>
#include <cstdint>

#define DIM     512
#define HEADS   8
#define DH      64
#define BATCH   8
#define NWIN    64
#define WSZ     64
#define NTOK    (BATCH * NWIN * WSZ)   // 32768

// Scratch (allocation-free rule: __device__ globals)
__device__ __half g_xh[(size_t)NTOK * DIM];                       // 33.5 MB
__device__ __half g_qkvh[(size_t)NTOK * 3 * DIM];                 // 100 MB
__device__ __half g_attnh[(size_t)NTOK * DIM];                    // 33.5 MB
__device__ __half g_wth[(size_t)(3 * DIM) * DIM + DIM * DIM];     // 2 MB (wqkvT, wprojT)

// ---------------------------------------------------------------------------
// helpers
// ---------------------------------------------------------------------------
__device__ __forceinline__ uint32_t smem_u32(const void* p) {
    uint32_t a;
    asm("{ .reg .u64 t; cvta.to.shared.u64 t, %1; cvt.u32.u64 %0, t; }"
        : "=r"(a) : "l"(p));
    return a;
}

__device__ __forceinline__ void cp16(uint32_t dst, const void* src) {
    asm volatile("cp.async.cg.shared.global [%0], [%1], 16;"
                 :: "r"(dst), "l"(src) : "memory");
}

__device__ __forceinline__ void ldsm4(unsigned r[4], uint32_t a) {
    asm volatile("ldmatrix.sync.aligned.m8n8.x4.shared.b16 {%0,%1,%2,%3}, [%4];"
                 : "=r"(r[0]), "=r"(r[1]), "=r"(r[2]), "=r"(r[3]) : "r"(a));
}

__device__ __forceinline__ void ldsm4t(unsigned r[4], uint32_t a) {
    asm volatile("ldmatrix.sync.aligned.m8n8.x4.trans.shared.b16 {%0,%1,%2,%3}, [%4];"
                 : "=r"(r[0]), "=r"(r[1]), "=r"(r[2]), "=r"(r[3]) : "r"(a));
}

__device__ __forceinline__ void mma_f16(float c[4], const unsigned a[4],
                                        const unsigned b[2]) {
    asm volatile(
        "mma.sync.aligned.m16n8k16.row.col.f32.f16.f16.f32 "
        "{%0,%1,%2,%3}, {%4,%5,%6,%7}, {%8,%9}, {%0,%1,%2,%3};"
        : "+f"(c[0]), "+f"(c[1]), "+f"(c[2]), "+f"(c[3])
        : "r"(a[0]), "r"(a[1]), "r"(a[2]), "r"(a[3]), "r"(b[0]), "r"(b[1]));
}

// ---------------------------------------------------------------------------
// Prologue: fp32 -> fp16 convert (x), fp32 -> fp16 transpose (weights)
// ---------------------------------------------------------------------------
__global__ void f2h_copy(const float* __restrict__ in, __half* __restrict__ out,
                         int n4)
{
    const int i = blockIdx.x * blockDim.x + threadIdx.x;
    if (i < n4) {
        float4 v = ((const float4*)in)[i];
        __half2* o = (__half2*)(out + (size_t)i * 4);
        o[0] = __floats2half2_rn(v.x, v.y);
        o[1] = __floats2half2_rn(v.z, v.w);
    }
}

__global__ void transpose_h(const float* __restrict__ in,
                            __half* __restrict__ out, int R, int C)
{
    __shared__ float t[32][33];
    const int tx = threadIdx.x, ty = threadIdx.y;
    const int x = blockIdx.x * 32 + tx;
    #pragma unroll
    for (int j = 0; j < 32; j += 8)
        t[ty + j][tx] = in[(size_t)(blockIdx.y * 32 + ty + j) * C + x];
    __syncthreads();
    const int x2 = blockIdx.y * 32 + tx;
    #pragma unroll
    for (int j = 0; j < 32; j += 8)
        out[(size_t)(blockIdx.x * 32 + ty + j) * R + x2] =
            __float2half_rn(t[tx][ty + j]);
}

// ---------------------------------------------------------------------------
// fp16 GEMM (templated): C[M,N] = A[M,K] @ Bt[N,K]^T (+bias).
// CTA tile 128 x (NFRAG*16), BK=64, 3-stage cp.async, 256 thr / 8 warps
// (4m x 2n), warp tile 32 x NFRAG*8. DBUF: software-pipelined fragment
// double-buffering (ldmatrix ks+1 issued before mma ks).
// ---------------------------------------------------------------------------
#define ST_H      72
#define NSTAGE    3
#define TILE_A    (128 * ST_H)

template<int NFRAG, bool DBUF>
__global__ __launch_bounds__(256, 2) void gemm_h(
    const __half* __restrict__ A, const __half* __restrict__ Bt,
    const float* __restrict__ bias, void* __restrict__ Cout,
    int M, int N, int K, int out_half)
{
    constexpr int BN     = NFRAG * 16;
    constexpr int TILE_B = BN * ST_H;
    constexpr int NB     = DBUF ? 2 : 1;

    extern __shared__ __align__(16) __half smh[];
    __half* As = smh;                           // [3][128][72]
    __half* Bs = smh + NSTAGE * TILE_A;         // [3][BN][72]
    const uint32_t as_a = smem_u32(As);
    const uint32_t bs_a = smem_u32(Bs);

    const int tid  = threadIdx.x;
    const int lane = tid & 31;
    const int wid  = tid >> 5;
    const int wm   = (wid & 3) * 32;
    const int wn   = (wid >> 2) * (NFRAG * 8);
    const int bm   = blockIdx.y * 128;
    const int bn   = blockIdx.x * BN;
    const int q    = lane & 3;
    const int g    = lane >> 2;

    const int m8  = lane & 7;
    const int sel = lane >> 3;
    uint32_t a_off[2], b_off[NFRAG / 2];
    #pragma unroll
    for (int mt = 0; mt < 2; mt++)
        a_off[mt] = (uint32_t)(((wm + mt * 16 + ((sel & 1) << 3) + m8) * ST_H
                                + ((sel >> 1) << 3)) * 2);
    #pragma unroll
    for (int p = 0; p < NFRAG / 2; p++)
        b_off[p] = (uint32_t)(((wn + ((p << 1) + (sel >> 1)) * 8 + m8) * ST_H
                               + ((sel & 1) << 3)) * 2);

    float acc[2][NFRAG][4];
    #pragma unroll
    for (int i = 0; i < 2; i++)
        #pragma unroll
        for (int j = 0; j < NFRAG; j++)
            #pragma unroll
            for (int k = 0; k < 4; k++) acc[i][j][k] = 0.f;

    unsigned afr[NB][2][4], bfr[NB][NFRAG][2];

    const int NT = K >> 6;

    #define LOAD_STAGE(kt_)                                                     \
    do {                                                                        \
        const int s_  = (kt_) % NSTAGE;                                         \
        const int k0_ = (kt_) * 64;                                             \
        _Pragma("unroll")                                                       \
        for (int i_ = tid; i_ < 512; i_ += 256) {                               \
            const int row_ = i_ >> 2;                                           \
            const int c_   = (i_ & 3) * 16;                                     \
            cp16(as_a + (uint32_t)(s_ * TILE_A + row_ * ST_H + c_) * 2,         \
                 A + (size_t)(bm + row_) * K + k0_ + c_);                       \
            cp16(as_a + (uint32_t)(s_ * TILE_A + row_ * ST_H + c_ + 8) * 2,     \
                 A + (size_t)(bm + row_) * K + k0_ + c_ + 8);                   \
        }                                                                       \
        _Pragma("unroll")                                                       \
        for (int i_ = tid; i_ < BN * 4; i_ += 256) {                            \
            const int row_ = i_ >> 2;                                           \
            const int c_   = (i_ & 3) * 16;                                     \
            cp16(bs_a + (uint32_t)(s_ * TILE_B + row_ * ST_H + c_) * 2,         \
                 Bt + (size_t)(bn + row_) * K + k0_ + c_);                      \
            cp16(bs_a + (uint32_t)(s_ * TILE_B + row_ * ST_H + c_ + 8) * 2,     \
                 Bt + (size_t)(bn + row_) * K + k0_ + c_ + 8);                  \
        }                                                                       \
        asm volatile("cp.async.commit_group;" ::: "memory");                    \
    } while (0)

    #define LDFRAG(ks_, bb_)                                                    \
    do {                                                                        \
        const uint32_t ko_ = (uint32_t)((ks_) * 32);                            \
        ldsm4(afr[bb_][0], sa + a_off[0] + ko_);                                \
        ldsm4(afr[bb_][1], sa + a_off[1] + ko_);                                \
        _Pragma("unroll")                                                       \
        for (int p_ = 0; p_ < NFRAG / 2; p_++) {                                \
            unsigned t_[4];                                                     \
            ldsm4(t_, sb + b_off[p_] + ko_);                                    \
            bfr[bb_][2 * p_][0] = t_[0]; bfr[bb_][2 * p_][1] = t_[1];           \
            bfr[bb_][2 * p_ + 1][0] = t_[2]; bfr[bb_][2 * p_ + 1][1] = t_[3];   \
        }                                                                       \
    } while (0)

    #define DOMMA(bb_)                                                          \
    do {                                                                        \
        _Pragma("unroll")                                                       \
        for (int mt_ = 0; mt_ < 2; mt_++)                                       \
            _Pragma("unroll")                                                   \
            for (int nt_ = 0; nt_ < NFRAG; nt_++)                               \
                mma_f16(acc[mt_][nt_], afr[bb_][mt_], bfr[bb_][nt_]);           \
    } while (0)

    LOAD_STAGE(0);
    LOAD_STAGE(1);

    for (int kt = 0; kt < NT; kt++) {
        if (kt < NT - 1)
            asm volatile("cp.async.wait_group 1;" ::: "memory");
        else
            asm volatile("cp.async.wait_group 0;" ::: "memory");
        __syncthreads();
        if (kt + 2 < NT) LOAD_STAGE(kt + 2);

        const int st = kt % NSTAGE;
        const uint32_t sa = as_a + (uint32_t)(st * TILE_A) * 2;
        const uint32_t sb = bs_a + (uint32_t)(st * TILE_B) * 2;

        if (DBUF) {
            LDFRAG(0, 0);
            #pragma unroll
            for (int ks = 0; ks < 4; ks++) {
                if (ks < 3) LDFRAG(ks + 1, (ks + 1) & (NB - 1));
                DOMMA(ks & (NB - 1));
            }
        } else {
            #pragma unroll
            for (int ks = 0; ks < 4; ks++) {
                LDFRAG(ks, 0);
                DOMMA(0);
            }
        }
    }

    // Epilogue: c0,c1 -> (row g, cols 2q,2q+1); c2,c3 -> row g+8.
    if (out_half) {
        __half* Ch = (__half*)Cout;
        #pragma unroll
        for (int nt = 0; nt < NFRAG; nt++) {
            const int col = bn + wn + nt * 8 + 2 * q;
            #pragma unroll
            for (int mt = 0; mt < 2; mt++) {
                const int r0 = bm + wm + mt * 16 + g;
                *(__half2*)(Ch + (size_t)r0 * N + col) =
                    __floats2half2_rn(acc[mt][nt][0], acc[mt][nt][1]);
                *(__half2*)(Ch + (size_t)(r0 + 8) * N + col) =
                    __floats2half2_rn(acc[mt][nt][2], acc[mt][nt][3]);
            }
        }
    } else {
        float* Cf = (float*)Cout;
        #pragma unroll
        for (int nt = 0; nt < NFRAG; nt++) {
            const int col = bn + wn + nt * 8 + 2 * q;
            float b0 = 0.f, b1 = 0.f;
            if (bias) { b0 = bias[col]; b1 = bias[col + 1]; }
            #pragma unroll
            for (int mt = 0; mt < 2; mt++) {
                const int r0 = bm + wm + mt * 16 + g;
                *(float2*)(Cf + (size_t)r0 * N + col) =
                    make_float2(acc[mt][nt][0] + b0, acc[mt][nt][1] + b1);
                *(float2*)(Cf + (size_t)(r0 + 8) * N + col) =
                    make_float2(acc[mt][nt][2] + b0, acc[mt][nt][3] + b1);
            }
        }
    }
    #undef LOAD_STAGE
    #undef LDFRAG
    #undef DOMMA
}

#define GEMM1_SMEM (NSTAGE * (TILE_A + 96  * ST_H) * 2)   // 96768 bytes
#define GEMM2_SMEM (NSTAGE * (TILE_A + 128 * ST_H) * 2)   // 110592 bytes

// ---------------------------------------------------------------------------
// Window attention: all-fp16 operands, mma.m16n8k16, ldmatrix (+.trans for V).
// One 128-thr block per (b,h,n). Warp w owns rows 16w..16w+15. (unchanged)
// ---------------------------------------------------------------------------
__global__ __launch_bounds__(128) void window_attn_h(
    const __half* __restrict__ qkv, __half* __restrict__ out)
{
    __shared__ __half Qh[64][ST_H];    // Q, then P
    __shared__ __half KVh[64][ST_H];   // K, then V

    const int tid  = threadIdx.x;
    const int lane = tid & 31;
    const int w    = tid >> 5;
    const int g    = lane >> 2;
    const int q    = lane & 3;
    const int m8   = lane & 7;
    const int sel  = lane >> 3;

    const int idx = blockIdx.x;
    const int n   = idx & 63;
    const int h   = (idx >> 6) & 7;
    const int b   = idx >> 9;
    const size_t tokbase = ((size_t)(b * NWIN + n) * WSZ) * (3 * DIM);

    const uint32_t qbase = smem_u32(Qh);
    const uint32_t kbase = smem_u32(KVh);

    uint4 vpre[4];
    #pragma unroll
    for (int i = 0; i < 4; i++) {
        const int lin = i * 128 + tid;
        const int row = lin >> 3;
        const int c8  = (lin & 7) * 8;
        const __half* src = qkv + tokbase + (size_t)row * (3 * DIM) + h * DH + c8;
        *(uint4*)&Qh[row][c8]  = *(const uint4*)src;
        *(uint4*)&KVh[row][c8] = *(const uint4*)(src + DIM);
        vpre[i] = *(const uint4*)(src + 2 * DIM);
    }
    __syncthreads();

    const uint32_t aoff =
        (uint32_t)(((w * 16 + ((sel & 1) << 3) + m8) * ST_H + ((sel >> 1) << 3)) * 2);
    uint32_t boff[4], voff[4];
    #pragma unroll
    for (int p = 0; p < 4; p++) {
        boff[p] = (uint32_t)(((((p << 1) + (sel >> 1)) * 8 + m8) * ST_H
                              + ((sel & 1) << 3)) * 2);
        voff[p] = (uint32_t)(((((sel & 1) << 3) + m8) * ST_H
                              + ((p << 1) + (sel >> 1)) * 8) * 2);
    }

    float sacc[8][4];
    #pragma unroll
    for (int nt = 0; nt < 8; nt++)
        #pragma unroll
        for (int j = 0; j < 4; j++) sacc[nt][j] = 0.f;

    #pragma unroll
    for (int ks = 0; ks < 4; ks++) {
        const uint32_t ko = (uint32_t)(ks * 32);
        unsigned a[4], bfr[8][2];
        ldsm4(a, qbase + aoff + ko);
        #pragma unroll
        for (int p = 0; p < 4; p++) {
            unsigned t[4];
            ldsm4(t, kbase + boff[p] + ko);
            bfr[2 * p][0] = t[0]; bfr[2 * p][1] = t[1];
            bfr[2 * p + 1][0] = t[2]; bfr[2 * p + 1][1] = t[3];
        }
        #pragma unroll
        for (int nt = 0; nt < 8; nt++)
            mma_f16(sacc[nt], a, bfr[nt]);
    }

    const float scale = 0.125f;
    float mx0 = -1e30f, mx1 = -1e30f;
    #pragma unroll
    for (int nt = 0; nt < 8; nt++) {
        #pragma unroll
        for (int j = 0; j < 4; j++) sacc[nt][j] *= scale;
        mx0 = fmaxf(mx0, fmaxf(sacc[nt][0], sacc[nt][1]));
        mx1 = fmaxf(mx1, fmaxf(sacc[nt][2], sacc[nt][3]));
    }
    mx0 = fmaxf(mx0, __shfl_xor_sync(0xffffffffu, mx0, 1));
    mx0 = fmaxf(mx0, __shfl_xor_sync(0xffffffffu, mx0, 2));
    mx1 = fmaxf(mx1, __shfl_xor_sync(0xffffffffu, mx1, 1));
    mx1 = fmaxf(mx1, __shfl_xor_sync(0xffffffffu, mx1, 2));

    float s0 = 0.f, s1 = 0.f;
    #pragma unroll
    for (int nt = 0; nt < 8; nt++) {
        sacc[nt][0] = __expf(sacc[nt][0] - mx0);
        sacc[nt][1] = __expf(sacc[nt][1] - mx0);
        sacc[nt][2] = __expf(sacc[nt][2] - mx1);
        sacc[nt][3] = __expf(sacc[nt][3] - mx1);
        s0 += sacc[nt][0] + sacc[nt][1];
        s1 += sacc[nt][2] + sacc[nt][3];
    }
    s0 += __shfl_xor_sync(0xffffffffu, s0, 1);
    s0 += __shfl_xor_sync(0xffffffffu, s0, 2);
    s1 += __shfl_xor_sync(0xffffffffu, s1, 1);
    s1 += __shfl_xor_sync(0xffffffffu, s1, 2);
    const float inv0 = 1.f / s0, inv1 = 1.f / s1;

    {
        const int r = w * 16 + g;
        #pragma unroll
        for (int nt = 0; nt < 8; nt++) {
            const int col = nt * 8 + 2 * q;
            *(__half2*)&Qh[r][col] =
                __floats2half2_rn(sacc[nt][0] * inv0, sacc[nt][1] * inv0);
            *(__half2*)&Qh[r + 8][col] =
                __floats2half2_rn(sacc[nt][2] * inv1, sacc[nt][3] * inv1);
        }
    }
    __syncthreads();

    #pragma unroll
    for (int i = 0; i < 4; i++) {
        const int lin = i * 128 + tid;
        const int row = lin >> 3;
        const int c8  = (lin & 7) * 8;
        *(uint4*)&KVh[row][c8] = vpre[i];
    }
    __syncthreads();

    float oacc[8][4];
    #pragma unroll
    for (int nt = 0; nt < 8; nt++)
        #pragma unroll
        for (int j = 0; j < 4; j++) oacc[nt][j] = 0.f;

    #pragma unroll
    for (int ks = 0; ks < 4; ks++) {
        const uint32_t ko  = (uint32_t)(ks * 32);
        const uint32_t kov = (uint32_t)(ks * 16 * ST_H * 2);
        unsigned a[4], bfr[8][2];
        ldsm4(a, qbase + aoff + ko);
        #pragma unroll
        for (int p = 0; p < 4; p++) {
            unsigned t[4];
            ldsm4t(t, kbase + voff[p] + kov);
            bfr[2 * p][0] = t[0]; bfr[2 * p][1] = t[1];
            bfr[2 * p + 1][0] = t[2]; bfr[2 * p + 1][1] = t[3];
        }
        #pragma unroll
        for (int nt = 0; nt < 8; nt++)
            mma_f16(oacc[nt], a, bfr[nt]);
    }

    const size_t obase = (((size_t)(b * HEADS + h) * NWIN + n) * WSZ) * DH;
    const int r = w * 16 + g;
    #pragma unroll
    for (int nt = 0; nt < 8; nt++) {
        const int col = nt * 8 + 2 * q;
        *(__half2*)(out + obase + (size_t)r * DH + col) =
            __floats2half2_rn(oacc[nt][0], oacc[nt][1]);
        *(__half2*)(out + obase + (size_t)(r + 8) * DH + col) =
            __floats2half2_rn(oacc[nt][2], oacc[nt][3]);
    }
}

// ---------------------------------------------------------------------------
extern "C" void kernel_launch(void* const* d_in, const int* in_sizes, int n_in,
                              void* d_out, int out_size)
{
    const float* x      = (const float*)d_in[0];  // [8,64,64,512]
    const float* w_qkv  = (const float*)d_in[1];  // [512,1536]
    const float* w_proj = (const float*)d_in[2];  // [512,512]
    const float* b_proj = (const float*)d_in[3];  // [512]
    float* out = (float*)d_out;                   // [8,64,64,512]

    __half *xh, *qkvh, *attnh, *wth;
    cudaGetSymbolAddress((void**)&xh,    g_xh);
    cudaGetSymbolAddress((void**)&qkvh,  g_qkvh);
    cudaGetSymbolAddress((void**)&attnh, g_attnh);
    cudaGetSymbolAddress((void**)&wth,   g_wth);
    __half* wqkvT_h  = wth;                            // [1536,512]
    __half* wprojT_h = wth + (size_t)(3 * DIM) * DIM;  // [512,512]

    static bool attr_set = false;
    if (!attr_set) {
        cudaFuncSetAttribute(gemm_h<6, true>,
                             cudaFuncAttributeMaxDynamicSharedMemorySize, GEMM1_SMEM);
        cudaFuncSetAttribute(gemm_h<8, false>,
                             cudaFuncAttributeMaxDynamicSharedMemorySize, GEMM2_SMEM);
        attr_set = true;
    }

    // 0) prologue: x -> half; weights -> transposed half
    {
        const int n4 = NTOK * DIM / 4;
        f2h_copy<<<(n4 + 255) / 256, 256>>>(x, xh, n4);
        dim3 blk(32, 8);
        transpose_h<<<dim3((3 * DIM) / 32, DIM / 32), blk>>>(w_qkv, wqkvT_h, DIM, 3 * DIM);
        transpose_h<<<dim3(DIM / 32, DIM / 32), blk>>>(w_proj, wprojT_h, DIM, DIM);
    }
    // 1) qkv = x @ w_qkv (fp16 in, fp16 out) — 128x96 tiles, dbl-buffered frags
    {
        dim3 grid((3 * DIM) / 96, NTOK / 128);
        gemm_h<6, true><<<grid, 256, GEMM1_SMEM>>>(xh, wqkvT_h, nullptr, qkvh,
                                                   NTOK, 3 * DIM, DIM, 1);
    }
    // 2) per-window attention -> [B,H,NW,W,dh] linear
    {
        window_attn_h<<<BATCH * HEADS * NWIN, 128>>>(qkvh, attnh);
    }
    // 3) out = attn_flat @ w_proj + b_proj (fp16 in, fp32 out) — R8 config
    {
        dim3 grid(DIM / 128, NTOK / 128);
        gemm_h<8, false><<<grid, 256, GEMM2_SMEM>>>(attnh, wprojT_h, b_proj, out,
                                                    NTOK, DIM, DIM, 0);
    }
}